// round 11
// baseline (speedup 1.0000x reference)
#include <cuda_runtime.h>
#include <cuda_fp16.h>
#include <cstdint>

#define T_TOK   4096
#define HID     1024
#define INTER   512
#define NE      64
#define NEZ     80
#define CAPACITY 320
#define SCALE_F 1.5f

// ---------------- scratch (static device globals; no allocation) ----------------
__device__ float    g_logits[(size_t)T_TOK * NEZ];
__device__ int      g_counts[NE];
__device__ int      g_rows[NE * CAPACITY];
__device__ int      g_tok_e[T_TOK * 2];
__device__ int      g_tok_p[T_TOK * 2];
__device__ float    g_tok_w[T_TOK * 2];
__device__ float    g_zeroc[T_TOK];
__device__ uint32_t g_hs16[(size_t)T_TOK * (HID / 2)];              // fp16 tokens, 8 MB
__device__ uint32_t g_gbuf32[(size_t)NE * CAPACITY * (INTER / 2)];  // fp16 k-pairs, 21 MB
__device__ uint32_t g_ybuf16[(size_t)NE * CAPACITY * (HID / 2)];    // fp16 n-pairs, 42 MB

// ---------------- helpers ----------------
__device__ __forceinline__ uint32_t pack_f16x2(float lo, float hi) {
    uint32_t r;
    asm("cvt.rn.f16x2.f32 %0, %1, %2;" : "=r"(r) : "f"(hi), "f"(lo));
    return r;
}
__device__ __forceinline__ void mma_f16(float* c, const uint32_t* a, uint32_t b0, uint32_t b1) {
    asm volatile(
        "mma.sync.aligned.m16n8k16.row.col.f32.f16.f16.f32 "
        "{%0,%1,%2,%3},{%4,%5,%6,%7},{%8,%9},{%0,%1,%2,%3};\n"
        : "+f"(c[0]), "+f"(c[1]), "+f"(c[2]), "+f"(c[3])
        : "r"(a[0]), "r"(a[1]), "r"(a[2]), "r"(a[3]), "r"(b0), "r"(b1));
}
__device__ __forceinline__ void ldsm_x4(uint32_t* r, uint32_t addr) {
    asm volatile("ldmatrix.sync.aligned.m8n8.x4.shared.b16 {%0,%1,%2,%3}, [%4];"
                 : "=r"(r[0]), "=r"(r[1]), "=r"(r[2]), "=r"(r[3]) : "r"(addr));
}
__device__ __forceinline__ void lds_v2(uint32_t& a, uint32_t& b, uint32_t addr) {
    asm volatile("ld.shared.v2.u32 {%0,%1}, [%2];" : "=r"(a), "=r"(b) : "r"(addr));
}
__device__ __forceinline__ void lds_u32(uint32_t& a, uint32_t addr) {
    asm volatile("ld.shared.u32 %0, [%1];" : "=r"(a) : "r"(addr));
}
__device__ __forceinline__ void cp_async16(uint32_t dst, const void* src, int src_bytes) {
    asm volatile("cp.async.cg.shared.global [%0], [%1], 16, %2;"
                 :: "r"(dst), "l"(src), "r"(src_bytes) : "memory");
}
__device__ __forceinline__ void cp_commit() {
    asm volatile("cp.async.commit_group;" ::: "memory");
}
__device__ __forceinline__ void cp_wait0() {
    asm volatile("cp.async.wait_group 0;" ::: "memory");
}

// ---------------- kernel 0: zero counters ----------------
__global__ void zero_counts_kernel() {
    if (threadIdx.x < NE) g_counts[threadIdx.x] = 0;
}

// ---------------- kernel 0b: hs -> fp16 pairs ----------------
__global__ void __launch_bounds__(256) cvt_hs_kernel(const float* __restrict__ hs) {
    size_t idx = (size_t)blockIdx.x * 256 + threadIdx.x;   // one u32 out per thread
    float2 v = ((const float2*)hs)[idx];
    g_hs16[idx] = pack_f16x2(v.x, v.y);
}

// ---------------- kernel 1: router GEMM (fp32 FFMA, exact selection path) ----------
__global__ void __launch_bounds__(256) router_gemm_kernel(
    const float* __restrict__ hs, const float* __restrict__ rw) {
    __shared__ float As[32][33];
    __shared__ float Ws[32][81];
    const int m0 = blockIdx.x * 32;
    const int tid = threadIdx.x;
    const int tm = tid & 15;
    const int tn = tid >> 4;

    float acc[2][5];
#pragma unroll
    for (int i = 0; i < 2; i++)
#pragma unroll
        for (int j = 0; j < 5; j++) acc[i][j] = 0.f;

    for (int k0 = 0; k0 < HID; k0 += 32) {
#pragma unroll
        for (int i = 0; i < 4; i++) {
            int lin = tid + i * 256;
            int k = lin & 31, m = lin >> 5;
            As[k][m] = hs[(size_t)(m0 + m) * HID + k0 + k];
        }
#pragma unroll
        for (int i = 0; i < 10; i++) {
            int lin = tid + i * 256;
            int k = lin & 31, n = lin >> 5;
            Ws[k][n] = rw[(size_t)n * HID + k0 + k];
        }
        __syncthreads();
#pragma unroll
        for (int kk = 0; kk < 32; kk++) {
            float a[2], w[5];
#pragma unroll
            for (int i = 0; i < 2; i++) a[i] = As[kk][tm + 16 * i];
#pragma unroll
            for (int j = 0; j < 5; j++) w[j] = Ws[kk][tn + 16 * j];
#pragma unroll
            for (int i = 0; i < 2; i++)
#pragma unroll
                for (int j = 0; j < 5; j++) acc[i][j] = fmaf(a[i], w[j], acc[i][j]);
        }
        __syncthreads();
    }
#pragma unroll
    for (int i = 0; i < 2; i++)
#pragma unroll
        for (int j = 0; j < 5; j++)
            g_logits[(size_t)(m0 + tm + 16 * i) * NEZ + tn + 16 * j] = acc[i][j];
}

// ---------------- kernel 2: sigmoid + top-2 + capacity dispatch ----------------
__global__ void topk_dispatch_kernel(const float* __restrict__ bias) {
    int t = blockIdx.x * blockDim.x + threadIdx.x;
    if (t >= T_TOK) return;

    float sc[NEZ];
    for (int e = 0; e < NEZ; e++) {
        float l = g_logits[(size_t)t * NEZ + e];
        sc[e] = 1.f / (1.f + expf(-l));
    }
    int i1 = -1, i2 = -1;
    float b1 = -1e30f, b2 = -1e30f;
    for (int e = 0; e < NEZ; e++) {
        float b = sc[e] + bias[e];
        if (b > b1) { b2 = b1; i2 = i1; b1 = b; i1 = e; }
        else if (b > b2) { b2 = b; i2 = e; }
    }

    float zc = 0.f;
    int sel[2] = {i1, i2};
#pragma unroll
    for (int k = 0; k < 2; k++) {
        int e = sel[k];
        float w = sc[e];
        if (e >= NE) {
            zc += w;
            g_tok_p[t * 2 + k] = -1;
            g_tok_e[t * 2 + k] = 0;
            g_tok_w[t * 2 + k] = 0.f;
        } else {
            int p = atomicAdd(&g_counts[e], 1);
            if (p < CAPACITY) g_rows[e * CAPACITY + p] = t;
            g_tok_p[t * 2 + k] = p;
            g_tok_e[t * 2 + k] = e;
            g_tok_w[t * 2 + k] = w;
        }
    }
    g_zeroc[t] = zc;
}

// ---------------- kernel 3: fused gate/up fp16 GEMM + SiLU -> g_gbuf32 -----------
// Tile 128M x 32N x 32K. 8 warps, each 32Mx16N of BOTH G and U (acc 32 floats).
// A via cp.async (fp16, zfill), B fp32->fp16 register staging, interleaved g/u smem.
#define GA_ABUF (128 * 20)          // u32 per A buffer
#define GA_BBUF (16 * 72)           // u32 per B buffer
__global__ void __launch_bounds__(256, 3) gemm_gateup_kernel(
    const float* __restrict__ wg,
    const float* __restrict__ wu) {
    const int e = blockIdx.z;
    const int Me = min(g_counts[e], CAPACITY);
    const int m0 = blockIdx.y * 128;
    if (m0 >= Me) return;
    const int n0 = blockIdx.x * 32;

    __shared__ uint32_t As32[2][GA_ABUF];   // fp16 kpairs [row][16 + 4 pad]
    __shared__ uint32_t Bgu[2][GA_BBUF];    // [kpair][n*2 {g,u}] stride 72
    __shared__ int toks[128];

    const int tid = threadIdx.x;
    const int lane = tid & 31, warp = tid >> 5;
    const int grp = lane >> 2, tg = lane & 3;
    const int wm = (warp >> 1) * 32, wn = (warp & 1) * 16;

    if (tid < 128) {
        int r = m0 + tid;
        toks[tid] = (r < Me) ? g_rows[e * CAPACITY + r] : -1;
    }
    __syncthreads();

    const uint32_t asBase = (uint32_t)__cvta_generic_to_shared(&As32[0][0]);
    const uint32_t bBase  = (uint32_t)__cvta_generic_to_shared(&Bgu[0][0]);

    // A cp.async: 2 slots/thread, 16B each. slot -> row = slot>>2, q = slot&3.
    const uint32_t* aSrc[2];
    int aOK[2];
    uint32_t aDst[2];
#pragma unroll
    for (int i = 0; i < 2; i++) {
        int slot = tid + i * 256;
        int row = slot >> 2, q = slot & 3;
        int tok = toks[row];
        aOK[i] = (tok >= 0) ? 16 : 0;
        aSrc[i] = g_hs16 + (size_t)max(tok, 0) * (HID / 2) + q * 4;
        aDst[i] = asBase + (uint32_t)(row * 20 + q * 4) * 4;
    }
    // B staging: j = kpair (0..15), n2 = 2 columns
    const int j = tid >> 4;
    const int n2 = (tid & 15) * 2;
    const float* gP = wg + (size_t)e * HID * INTER + (size_t)(2 * j) * INTER + n0 + n2;
    const float* uP = wu + (size_t)e * HID * INTER + (size_t)(2 * j) * INTER + n0 + n2;
    const int bDst = j * 72 + n2 * 2;

    const int rowoff = lane & 15;
    uint32_t aAddr[2];
#pragma unroll
    for (int mi = 0; mi < 2; mi++)
        aAddr[mi] = asBase + (uint32_t)((wm + mi * 16 + rowoff) * 20) * 4 + ((lane >= 16) ? 16 : 0);

    float2 gR0, gR1, uR0, uR1;
    auto issueA = [&](int buf, int kp) {   // kp = kpair (u32) offset
#pragma unroll
        for (int i = 0; i < 2; i++)
            cp_async16(aDst[i] + (uint32_t)buf * (GA_ABUF * 4), aSrc[i] + kp, aOK[i]);
        cp_commit();
    };
    auto fetchB = [&](int k0) {
        gR0 = *(const float2*)(gP + (size_t)k0 * INTER);
        gR1 = *(const float2*)(gP + (size_t)(k0 + 1) * INTER);
        uR0 = *(const float2*)(uP + (size_t)k0 * INTER);
        uR1 = *(const float2*)(uP + (size_t)(k0 + 1) * INTER);
    };
    auto stageB = [&](int buf) {
        uint4 v = make_uint4(pack_f16x2(gR0.x, gR1.x), pack_f16x2(uR0.x, uR1.x),
                             pack_f16x2(gR0.y, gR1.y), pack_f16x2(uR0.y, uR1.y));
        *(uint4*)&Bgu[buf][bDst] = v;
    };

    float accG[2][2][4], accU[2][2][4];
#pragma unroll
    for (int a = 0; a < 2; a++)
#pragma unroll
        for (int b = 0; b < 2; b++)
#pragma unroll
            for (int c = 0; c < 4; c++) { accG[a][b][c] = 0.f; accU[a][b][c] = 0.f; }

    issueA(0, 0);
    fetchB(0);
    stageB(0);
    cp_wait0();
    __syncthreads();

    const int KT = HID / 32;   // 32
    for (int kt = 0; kt < KT; kt++) {
        const int p = kt & 1;
        const uint32_t aOff = (uint32_t)p * (GA_ABUF * 4);
        const uint32_t bOff = (uint32_t)p * (GA_BBUF * 4);
        if (kt + 1 < KT) {
            issueA(p ^ 1, (kt + 1) * 16);
            fetchB((kt + 1) * 32);
        }
#pragma unroll
        for (int kb = 0; kb < 2; kb++) {
            const int p0 = kb * 8;
            uint32_t af[2][4];
            ldsm_x4(af[0], aAddr[0] + aOff + kb * 32);
            ldsm_x4(af[1], aAddr[1] + aOff + kb * 32);
#pragma unroll
            for (int ni = 0; ni < 2; ni++) {
                int nc2 = (wn + ni * 8 + grp) * 2;
                uint32_t bg0, bu0, bg1, bu1;
                lds_v2(bg0, bu0, bBase + bOff + (uint32_t)((p0 + tg) * 72 + nc2) * 4);
                lds_v2(bg1, bu1, bBase + bOff + (uint32_t)((p0 + tg + 4) * 72 + nc2) * 4);
#pragma unroll
                for (int mi = 0; mi < 2; mi++) {
                    mma_f16(accG[mi][ni], af[mi], bg0, bg1);
                    mma_f16(accU[mi][ni], af[mi], bu0, bu1);
                }
            }
        }
        if (kt + 1 < KT) stageB(p ^ 1);
        cp_wait0();
        __syncthreads();
    }

    // epilogue: silu(g)*u -> fp16 pairs
    uint32_t* gout = g_gbuf32 + (size_t)e * CAPACITY * (INTER / 2);
#pragma unroll
    for (int mi = 0; mi < 2; mi++) {
#pragma unroll
        for (int half = 0; half < 2; half++) {
            int mrow = m0 + wm + mi * 16 + grp + half * 8;
            if (mrow < Me) {
#pragma unroll
                for (int ni = 0; ni < 2; ni++) {
                    int n = n0 + wn + ni * 8 + tg * 2;
                    float gv0 = accG[mi][ni][half * 2 + 0];
                    float gv1 = accG[mi][ni][half * 2 + 1];
                    float uv0 = accU[mi][ni][half * 2 + 0];
                    float uv1 = accU[mi][ni][half * 2 + 1];
                    float o0 = (gv0 / (1.f + __expf(-gv0))) * uv0;
                    float o1 = (gv1 / (1.f + __expf(-gv1))) * uv1;
                    gout[(size_t)mrow * (INTER / 2) + (n >> 1)] = pack_f16x2(o0, o1);
                }
            }
        }
    }
}

// ---------------- kernel 4: down-proj fp16 GEMM -> y_buf (fp16) ----------------
// Tile 128M x 64N x 32K. 8 warps of 32x32 (acc 32). A via cp.async from g_gbuf32.
#define DN_ABUF (128 * 20)
#define DN_BBUF (16 * 72)
__global__ void __launch_bounds__(256, 3) gemm_down_kernel(const float* __restrict__ wd) {
    const int e = blockIdx.z;
    const int Me = min(g_counts[e], CAPACITY);
    const int m0 = blockIdx.y * 128;
    if (m0 >= Me) return;
    const int n0 = blockIdx.x * 64;

    __shared__ uint32_t As32[2][DN_ABUF];
    __shared__ uint32_t Bs32[2][DN_BBUF];   // [kpair][64 n + 8 pad]

    const int tid = threadIdx.x;
    const int lane = tid & 31, warp = tid >> 5;
    const int grp = lane >> 2, tg = lane & 3;
    const int wm = (warp >> 1) * 32, wn = (warp & 1) * 32;

    const uint32_t asBase = (uint32_t)__cvta_generic_to_shared(&As32[0][0]);
    const uint32_t bBase  = (uint32_t)__cvta_generic_to_shared(&Bs32[0][0]);

    const uint32_t* gA = g_gbuf32 + ((size_t)e * CAPACITY + m0) * (INTER / 2);
    const uint32_t* aSrc[2];
    int aOK[2];
    uint32_t aDst[2];
#pragma unroll
    for (int i = 0; i < 2; i++) {
        int slot = tid + i * 256;
        int row = slot >> 2, q = slot & 3;
        aOK[i] = (m0 + row < CAPACITY) ? 16 : 0;
        aSrc[i] = gA + (size_t)row * (INTER / 2) + q * 4;
        aDst[i] = asBase + (uint32_t)(row * 20 + q * 4) * 4;
    }
    const int j = tid >> 4;
    const int n4 = (tid & 15) * 4;
    const float* bP = wd + (size_t)e * INTER * HID + (size_t)(2 * j) * HID + n0 + n4;
    const int bDst = j * 72 + n4;

    const int rowoff = lane & 15;
    uint32_t aAddr[2];
#pragma unroll
    for (int mi = 0; mi < 2; mi++)
        aAddr[mi] = asBase + (uint32_t)((wm + mi * 16 + rowoff) * 20) * 4 + ((lane >= 16) ? 16 : 0);

    float4 bR0, bR1;
    auto issueA = [&](int buf, int kp) {
#pragma unroll
        for (int i = 0; i < 2; i++)
            cp_async16(aDst[i] + (uint32_t)buf * (DN_ABUF * 4), aSrc[i] + kp, aOK[i]);
        cp_commit();
    };
    auto fetchB = [&](int k0) {
        bR0 = *(const float4*)(bP + (size_t)k0 * HID);
        bR1 = *(const float4*)(bP + (size_t)(k0 + 1) * HID);
    };
    auto stageB = [&](int buf) {
        uint4 v = make_uint4(pack_f16x2(bR0.x, bR1.x), pack_f16x2(bR0.y, bR1.y),
                             pack_f16x2(bR0.z, bR1.z), pack_f16x2(bR0.w, bR1.w));
        *(uint4*)&Bs32[buf][bDst] = v;
    };

    float acc[2][4][4];
#pragma unroll
    for (int a = 0; a < 2; a++)
#pragma unroll
        for (int b = 0; b < 4; b++)
#pragma unroll
            for (int c = 0; c < 4; c++) acc[a][b][c] = 0.f;

    issueA(0, 0);
    fetchB(0);
    stageB(0);
    cp_wait0();
    __syncthreads();

    const int KT = INTER / 32;   // 16
    for (int kt = 0; kt < KT; kt++) {
        const int p = kt & 1;
        const uint32_t aOff = (uint32_t)p * (DN_ABUF * 4);
        const uint32_t bOff = (uint32_t)p * (DN_BBUF * 4);
        if (kt + 1 < KT) {
            issueA(p ^ 1, (kt + 1) * 16);
            fetchB((kt + 1) * 32);
        }
#pragma unroll
        for (int kb = 0; kb < 2; kb++) {
            const int p0 = kb * 8;
            uint32_t af[2][4];
            ldsm_x4(af[0], aAddr[0] + aOff + kb * 32);
            ldsm_x4(af[1], aAddr[1] + aOff + kb * 32);
#pragma unroll
            for (int ni = 0; ni < 4; ni++) {
                int nc = wn + ni * 8 + grp;
                uint32_t b0, b1;
                lds_u32(b0, bBase + bOff + (uint32_t)((p0 + tg) * 72 + nc) * 4);
                lds_u32(b1, bBase + bOff + (uint32_t)((p0 + tg + 4) * 72 + nc) * 4);
#pragma unroll
                for (int mi = 0; mi < 2; mi++) mma_f16(acc[mi][ni], af[mi], b0, b1);
            }
        }
        if (kt + 1 < KT) stageB(p ^ 1);
        cp_wait0();
        __syncthreads();
    }

    uint32_t* yout = g_ybuf16 + (size_t)e * CAPACITY * (HID / 2);
#pragma unroll
    for (int mi = 0; mi < 2; mi++) {
#pragma unroll
        for (int half = 0; half < 2; half++) {
            int mrow = m0 + wm + mi * 16 + grp + half * 8;
            if (mrow < Me) {
#pragma unroll
                for (int ni = 0; ni < 4; ni++) {
                    int n = n0 + wn + ni * 8 + tg * 2;
                    yout[(size_t)mrow * (HID / 2) + (n >> 1)] =
                        pack_f16x2(acc[mi][ni][half * 2 + 0], acc[mi][ni][half * 2 + 1]);
                }
            }
        }
    }
}

// ---------------- kernel 5: deterministic combine (fp16 y) ----------------
__global__ void combine_kernel(const float* __restrict__ hs, float* __restrict__ out) {
    const int t = blockIdx.x;
    const int j = threadIdx.x;
    float4 hv = *(const float4*)(hs + (size_t)t * HID + j * 4);
    float zc = g_zeroc[t];
    float4 r;
    r.x = zc * hv.x; r.y = zc * hv.y; r.z = zc * hv.z; r.w = zc * hv.w;
#pragma unroll
    for (int k = 0; k < 2; k++) {
        int p = g_tok_p[t * 2 + k];
        if (p >= 0 && p < CAPACITY) {
            int e = g_tok_e[t * 2 + k];
            float w = g_tok_w[t * 2 + k];
            uint2 yp = *(const uint2*)(g_ybuf16 + ((size_t)e * CAPACITY + p) * (HID / 2) + j * 2);
            float2 y0 = __half22float2(*(const __half2*)&yp.x);
            float2 y1 = __half22float2(*(const __half2*)&yp.y);
            r.x = fmaf(w, y0.x, r.x);
            r.y = fmaf(w, y0.y, r.y);
            r.z = fmaf(w, y1.x, r.z);
            r.w = fmaf(w, y1.y, r.w);
        }
    }
    r.x *= SCALE_F; r.y *= SCALE_F; r.z *= SCALE_F; r.w *= SCALE_F;
    *(float4*)(out + (size_t)t * HID + j * 4) = r;
}

// ---------------- launcher ----------------
extern "C" void kernel_launch(void* const* d_in, const int* in_sizes, int n_in,
                              void* d_out, int out_size) {
    const float* hs   = (const float*)d_in[0];   // [4096,1024]
    const float* rw   = (const float*)d_in[1];   // [80,1024]
    const float* bias = (const float*)d_in[2];   // [80]
    const float* wg   = (const float*)d_in[3];   // [64,1024,512]
    const float* wu   = (const float*)d_in[4];   // [64,1024,512]
    const float* wd   = (const float*)d_in[5];   // [64,512,1024]
    float* out = (float*)d_out;                  // [4096,1024]

    zero_counts_kernel<<<1, 64>>>();
    cvt_hs_kernel<<<(T_TOK * HID / 2) / 256, 256>>>(hs);
    router_gemm_kernel<<<T_TOK / 32, 256>>>(hs, rw);
    topk_dispatch_kernel<<<T_TOK / 128, 128>>>(bias);
    gemm_gateup_kernel<<<dim3(INTER / 32, (CAPACITY + 127) / 128, NE), 256>>>(wg, wu);
    gemm_down_kernel<<<dim3(HID / 64, (CAPACITY + 127) / 128, NE), 256>>>(wd);
    combine_kernel<<<T_TOK, 256>>>(hs, out);
}

// round 12
// speedup vs baseline: 1.2308x; 1.2308x over previous
#include <cuda_runtime.h>
#include <cuda_fp16.h>
#include <cstdint>

#define T_TOK   4096
#define HID     1024
#define INTER   512
#define NE      64
#define NEZ     80
#define CAPACITY 320
#define SCALE_F 1.5f

// ---------------- scratch (static device globals; no allocation) ----------------
__device__ float    g_logits[(size_t)T_TOK * NEZ];
__device__ int      g_counts[NE];
__device__ int      g_rows[NE * CAPACITY];
__device__ int      g_tok_e[T_TOK * 2];
__device__ int      g_tok_p[T_TOK * 2];
__device__ float    g_tok_w[T_TOK * 2];
__device__ float    g_zeroc[T_TOK];
__device__ uint32_t g_gbuf32[(size_t)NE * CAPACITY * (INTER / 2)];  // fp16 k-pairs, 21 MB
__device__ uint32_t g_ybuf16[(size_t)NE * CAPACITY * (HID / 2)];    // fp16 n-pairs, 42 MB

// ---------------- helpers ----------------
__device__ __forceinline__ uint32_t pack_f16x2(float lo, float hi) {
    uint32_t r;
    asm("cvt.rn.f16x2.f32 %0, %1, %2;" : "=r"(r) : "f"(hi), "f"(lo));
    return r;
}
__device__ __forceinline__ void mma_f16(float* c, const uint32_t* a, uint32_t b0, uint32_t b1) {
    asm volatile(
        "mma.sync.aligned.m16n8k16.row.col.f32.f16.f16.f32 "
        "{%0,%1,%2,%3},{%4,%5,%6,%7},{%8,%9},{%0,%1,%2,%3};\n"
        : "+f"(c[0]), "+f"(c[1]), "+f"(c[2]), "+f"(c[3])
        : "r"(a[0]), "r"(a[1]), "r"(a[2]), "r"(a[3]), "r"(b0), "r"(b1));
}
__device__ __forceinline__ void ldsm_x4(uint32_t* r, uint32_t addr) {
    asm volatile("ldmatrix.sync.aligned.m8n8.x4.shared.b16 {%0,%1,%2,%3}, [%4];"
                 : "=r"(r[0]), "=r"(r[1]), "=r"(r[2]), "=r"(r[3]) : "r"(addr));
}
__device__ __forceinline__ void lds_v2(uint32_t& a, uint32_t& b, uint32_t addr) {
    asm volatile("ld.shared.v2.u32 {%0,%1}, [%2];" : "=r"(a), "=r"(b) : "r"(addr));
}

// ---------------- kernel 1: router GEMM (fp32 FFMA, exact selection path) ----------
// BM=32 tokens -> 128 blocks. Block 0 also zeroes the expert counters (topk runs later).
__global__ void __launch_bounds__(256) router_gemm_kernel(
    const float* __restrict__ hs, const float* __restrict__ rw) {
    __shared__ float As[32][33];
    __shared__ float Ws[32][81];
    const int m0 = blockIdx.x * 32;
    const int tid = threadIdx.x;
    const int tm = tid & 15;
    const int tn = tid >> 4;

    if (blockIdx.x == 0 && tid < NE) g_counts[tid] = 0;

    float acc[2][5];
#pragma unroll
    for (int i = 0; i < 2; i++)
#pragma unroll
        for (int j = 0; j < 5; j++) acc[i][j] = 0.f;

    for (int k0 = 0; k0 < HID; k0 += 32) {
#pragma unroll
        for (int i = 0; i < 4; i++) {                // 32x32 A tile
            int lin = tid + i * 256;
            int k = lin & 31, m = lin >> 5;
            As[k][m] = hs[(size_t)(m0 + m) * HID + k0 + k];
        }
#pragma unroll
        for (int i = 0; i < 10; i++) {               // 80x32 W tile
            int lin = tid + i * 256;
            int k = lin & 31, n = lin >> 5;
            Ws[k][n] = rw[(size_t)n * HID + k0 + k];
        }
        __syncthreads();
#pragma unroll
        for (int kk = 0; kk < 32; kk++) {
            float a[2], w[5];
#pragma unroll
            for (int i = 0; i < 2; i++) a[i] = As[kk][tm + 16 * i];
#pragma unroll
            for (int j = 0; j < 5; j++) w[j] = Ws[kk][tn + 16 * j];
#pragma unroll
            for (int i = 0; i < 2; i++)
#pragma unroll
                for (int j = 0; j < 5; j++) acc[i][j] = fmaf(a[i], w[j], acc[i][j]);
        }
        __syncthreads();
    }
#pragma unroll
    for (int i = 0; i < 2; i++)
#pragma unroll
        for (int j = 0; j < 5; j++)
            g_logits[(size_t)(m0 + tm + 16 * i) * NEZ + tn + 16 * j] = acc[i][j];
}

// ---------------- kernel 2: warp-per-token sigmoid + top-2 + dispatch ----------------
// better(x,xi, y,yi): strict >, lower index wins ties (jax.lax.top_k order).
__device__ __forceinline__ bool tk_better(float x, int xi, float y, int yi) {
    return (x > y) || (x == y && xi < yi);
}
__global__ void __launch_bounds__(256) topk_dispatch_kernel(const float* __restrict__ bias) {
    const int warp = threadIdx.x >> 5;
    const int lane = threadIdx.x & 31;
    const int t = blockIdx.x * 8 + warp;
    if (t >= T_TOK) return;

    // lane-local top-2 over experts {lane, lane+32, lane+64} (biased == sc: bias passed anyway)
    float b1 = -1e30f, b2 = -1e30f;
    int i1 = NEZ, i2 = NEZ;
#pragma unroll
    for (int c = 0; c < 3; c++) {
        int e = lane + 32 * c;
        if (e < NEZ) {
            float l = g_logits[(size_t)t * NEZ + e];
            float s = 1.f / (1.f + expf(-l));
            float b = s + bias[e];
            if (tk_better(b, e, b1, i1)) { b2 = b1; i2 = i1; b1 = b; i1 = e; }
            else if (tk_better(b, e, b2, i2)) { b2 = b; i2 = e; }
        }
    }
    // butterfly merge of (b1,i1,b2,i2) pairs
#pragma unroll
    for (int ofs = 16; ofs > 0; ofs >>= 1) {
        float c1 = __shfl_xor_sync(0xFFFFFFFF, b1, ofs);
        int   ci1 = __shfl_xor_sync(0xFFFFFFFF, i1, ofs);
        float c2 = __shfl_xor_sync(0xFFFFFFFF, b2, ofs);
        int   ci2 = __shfl_xor_sync(0xFFFFFFFF, i2, ofs);
        if (tk_better(c1, ci1, b1, i1)) {
            // c1 is new best; second = better of (old best, c2)
            if (tk_better(b1, i1, c2, ci2)) { b2 = b1; i2 = i1; }
            else { b2 = c2; i2 = ci2; }
            b1 = c1; i1 = ci1;
        } else {
            if (tk_better(c1, ci1, b2, i2)) { b2 = c1; i2 = ci1; }
        }
    }

    if (lane == 0) {
        float zc = 0.f;
        int sel[2] = {i1, i2};
#pragma unroll
        for (int k = 0; k < 2; k++) {
            int e = sel[k];
            // unbiased score of selected expert
            float l = g_logits[(size_t)t * NEZ + e];
            float w = 1.f / (1.f + expf(-l));
            if (e >= NE) {
                zc += w;
                g_tok_p[t * 2 + k] = -1;
                g_tok_e[t * 2 + k] = 0;
                g_tok_w[t * 2 + k] = 0.f;
            } else {
                int p = atomicAdd(&g_counts[e], 1);
                if (p < CAPACITY) g_rows[e * CAPACITY + p] = t;
                g_tok_p[t * 2 + k] = p;
                g_tok_e[t * 2 + k] = e;
                g_tok_w[t * 2 + k] = w;
            }
        }
        g_zeroc[t] = zc;
    }
}

// ---------------- kernel 3: fused gate/up fp16 GEMM + SiLU -> g_gbuf32 -----------
// Tile 128M x 64N x 32K. 8 warps of 32x32. ldmatrix A, interleaved g/u B (LDS.64).
__global__ void __launch_bounds__(256, 2) gemm_gateup_kernel(
    const float* __restrict__ hs,
    const float* __restrict__ wg,
    const float* __restrict__ wu) {
    const int e = blockIdx.z;
    const int Me = min(g_counts[e], CAPACITY);
    const int m0 = blockIdx.y * 128;
    if (m0 >= Me) return;
    const int n0 = blockIdx.x * 64;

    __shared__ uint32_t As32[2][128 * 20];   // [row][16 kpairs + 4 pad]
    __shared__ uint32_t Bgu[2][16 * 152];    // [kpair][n*2 {g,u}], stride 152
    __shared__ int toks[128];

    const int tid = threadIdx.x;
    const int lane = tid & 31, warp = tid >> 5;
    const int grp = lane >> 2, tg = lane & 3;
    const int wm = (warp >> 1) * 32, wn = (warp & 1) * 32;

    if (tid < 128) {
        int r = m0 + tid;
        toks[tid] = (r < Me) ? g_rows[e * CAPACITY + r] : -1;
    }
    __syncthreads();

    const float* aP[4];
    int aDst[4];
#pragma unroll
    for (int i = 0; i < 4; i++) {
        int slot = tid + i * 256;
        int row = slot >> 3, fq = slot & 7;
        int tok = toks[row];
        aP[i] = (tok >= 0) ? hs + (size_t)tok * HID + fq * 4 : (const float*)0;
        aDst[i] = row * 20 + fq * 2;
    }
    const int j = tid >> 4;
    const int n4 = (tid & 15) * 4;
    const float* gP = wg + (size_t)e * HID * INTER + (size_t)(2 * j) * INTER + n0 + n4;
    const float* uP = wu + (size_t)e * HID * INTER + (size_t)(2 * j) * INTER + n0 + n4;
    const int bDst = j * 152 + n4 * 2;

    const uint32_t asBase = (uint32_t)__cvta_generic_to_shared(&As32[0][0]);
    const uint32_t bBase  = (uint32_t)__cvta_generic_to_shared(&Bgu[0][0]);
    const int rowoff = lane & 15;
    uint32_t aAddr[2];
#pragma unroll
    for (int mi = 0; mi < 2; mi++)
        aAddr[mi] = asBase + (uint32_t)((wm + mi * 16 + rowoff) * 20) * 4 + ((lane >= 16) ? 16 : 0);

    float4 aR[4], gR0, gR1, uR0, uR1;
    auto fetch = [&](int k0) {
#pragma unroll
        for (int i = 0; i < 4; i++)
            aR[i] = aP[i] ? *(const float4*)(aP[i] + k0) : make_float4(0.f, 0.f, 0.f, 0.f);
        gR0 = *(const float4*)(gP + (size_t)k0 * INTER);
        gR1 = *(const float4*)(gP + (size_t)(k0 + 1) * INTER);
        uR0 = *(const float4*)(uP + (size_t)k0 * INTER);
        uR1 = *(const float4*)(uP + (size_t)(k0 + 1) * INTER);
    };
    auto stage = [&](int buf) {
#pragma unroll
        for (int i = 0; i < 4; i++) {
            uint2 v = make_uint2(pack_f16x2(aR[i].x, aR[i].y), pack_f16x2(aR[i].z, aR[i].w));
            *(uint2*)&As32[buf][aDst[i]] = v;
        }
        uint4 v0 = make_uint4(pack_f16x2(gR0.x, gR1.x), pack_f16x2(uR0.x, uR1.x),
                              pack_f16x2(gR0.y, gR1.y), pack_f16x2(uR0.y, uR1.y));
        uint4 v1 = make_uint4(pack_f16x2(gR0.z, gR1.z), pack_f16x2(uR0.z, uR1.z),
                              pack_f16x2(gR0.w, gR1.w), pack_f16x2(uR0.w, uR1.w));
        *(uint4*)&Bgu[buf][bDst] = v0;
        *(uint4*)&Bgu[buf][bDst + 4] = v1;
    };

    float accG[2][4][4], accU[2][4][4];
#pragma unroll
    for (int a = 0; a < 2; a++)
#pragma unroll
        for (int b = 0; b < 4; b++)
#pragma unroll
            for (int c = 0; c < 4; c++) { accG[a][b][c] = 0.f; accU[a][b][c] = 0.f; }

    fetch(0);
    stage(0);
    __syncthreads();

    const int KT = HID / 32;   // 32
    for (int kt = 0; kt < KT; kt++) {
        const int p = kt & 1;
        const uint32_t aOff = (uint32_t)p * (128 * 20 * 4);
        const uint32_t bOff = (uint32_t)p * (16 * 152 * 4);
        if (kt + 1 < KT) fetch((kt + 1) * 32);
#pragma unroll
        for (int kb = 0; kb < 2; kb++) {
            const int p0 = kb * 8;
            uint32_t af[2][4];
            ldsm_x4(af[0], aAddr[0] + aOff + kb * 32);
            ldsm_x4(af[1], aAddr[1] + aOff + kb * 32);
#pragma unroll
            for (int ni = 0; ni < 4; ni++) {
                int nc = wn + ni * 8 + grp;
                uint32_t bg0, bu0, bg1, bu1;
                lds_v2(bg0, bu0, bBase + bOff + (uint32_t)((p0 + tg) * 152 + nc * 2) * 4);
                lds_v2(bg1, bu1, bBase + bOff + (uint32_t)((p0 + tg + 4) * 152 + nc * 2) * 4);
#pragma unroll
                for (int mi = 0; mi < 2; mi++) {
                    mma_f16(accG[mi][ni], af[mi], bg0, bg1);
                    mma_f16(accU[mi][ni], af[mi], bu0, bu1);
                }
            }
        }
        if (kt + 1 < KT) stage(p ^ 1);
        __syncthreads();
    }

    uint32_t* gout = g_gbuf32 + (size_t)e * CAPACITY * (INTER / 2);
#pragma unroll
    for (int mi = 0; mi < 2; mi++) {
#pragma unroll
        for (int half = 0; half < 2; half++) {
            int mrow = m0 + wm + mi * 16 + grp + half * 8;
            if (mrow < Me) {
#pragma unroll
                for (int ni = 0; ni < 4; ni++) {
                    int n = n0 + wn + ni * 8 + tg * 2;
                    float gv0 = accG[mi][ni][half * 2 + 0];
                    float gv1 = accG[mi][ni][half * 2 + 1];
                    float uv0 = accU[mi][ni][half * 2 + 0];
                    float uv1 = accU[mi][ni][half * 2 + 1];
                    float o0 = (gv0 / (1.f + __expf(-gv0))) * uv0;
                    float o1 = (gv1 / (1.f + __expf(-gv1))) * uv1;
                    gout[(size_t)mrow * (INTER / 2) + (n >> 1)] = pack_f16x2(o0, o1);
                }
            }
        }
    }
}

// ---------------- kernel 4: down-proj fp16 GEMM -> y_buf (fp16) ----------------
// Tile 128M x 128N x 32K. 8 warps, each 32x64 (2 mi x 8 ni). ldmatrix A.
__global__ void __launch_bounds__(256, 2) gemm_down_kernel(const float* __restrict__ wd) {
    const int e = blockIdx.z;
    const int Me = min(g_counts[e], CAPACITY);
    const int m0 = blockIdx.y * 128;
    if (m0 >= Me) return;
    const int n0 = blockIdx.x * 128;

    __shared__ uint32_t As32[2][128 * 20];   // fp16 kpairs [row][16+4pad]
    __shared__ uint32_t Bs32[2][16 * 136];   // [kpair][128 n + 8 pad]

    const int tid = threadIdx.x;
    const int lane = tid & 31, warp = tid >> 5;
    const int grp = lane >> 2, tg = lane & 3;
    const int wm = (warp & 3) * 32, wn = (warp >> 2) * 64;

    const uint32_t* gA = g_gbuf32 + ((size_t)e * CAPACITY + m0) * (INTER / 2);
    const uint32_t* aP[2];
    int aDst[2];
#pragma unroll
    for (int i = 0; i < 2; i++) {
        int slot = tid + i * 256;
        int row = slot & 127, chunk = slot >> 7;
        aP[i] = (m0 + row < CAPACITY) ? gA + (size_t)row * (INTER / 2) + chunk * 4 : (const uint32_t*)0;
        aDst[i] = row * 20 + chunk * 4;
    }
    const float* wdBase = wd + (size_t)e * INTER * HID + n0;
    const float* bP[2];
    int bDst[2];
#pragma unroll
    for (int i = 0; i < 2; i++) {
        int slot = tid + i * 256;
        int jj = slot >> 5, ng = slot & 31;
        bP[i] = wdBase + (size_t)(2 * jj) * HID + ng * 4;
        bDst[i] = jj * 136 + ng * 4;
    }

    const uint32_t asBase = (uint32_t)__cvta_generic_to_shared(&As32[0][0]);
    const int rowoff = lane & 15;
    uint32_t aAddr[2];
#pragma unroll
    for (int mi = 0; mi < 2; mi++)
        aAddr[mi] = asBase + (uint32_t)((wm + mi * 16 + rowoff) * 20) * 4 + ((lane >= 16) ? 16 : 0);

    uint4 aR[2];
    float4 bR0[2], bR1[2];
    auto fetch = [&](int kt16) {
#pragma unroll
        for (int i = 0; i < 2; i++)
            aR[i] = aP[i] ? *(const uint4*)(aP[i] + kt16) : make_uint4(0u, 0u, 0u, 0u);
#pragma unroll
        for (int i = 0; i < 2; i++) {
            bR0[i] = *(const float4*)(bP[i] + (size_t)(kt16 * 2) * HID);
            bR1[i] = *(const float4*)(bP[i] + (size_t)(kt16 * 2 + 1) * HID);
        }
    };
    auto stage = [&](int buf) {
#pragma unroll
        for (int i = 0; i < 2; i++)
            *(uint4*)&As32[buf][aDst[i]] = aR[i];
#pragma unroll
        for (int i = 0; i < 2; i++) {
            uint4 vb = make_uint4(pack_f16x2(bR0[i].x, bR1[i].x), pack_f16x2(bR0[i].y, bR1[i].y),
                                  pack_f16x2(bR0[i].z, bR1[i].z), pack_f16x2(bR0[i].w, bR1[i].w));
            *(uint4*)&Bs32[buf][bDst[i]] = vb;
        }
    };

    float acc[2][8][4];
#pragma unroll
    for (int a = 0; a < 2; a++)
#pragma unroll
        for (int b = 0; b < 8; b++)
#pragma unroll
            for (int c = 0; c < 4; c++) acc[a][b][c] = 0.f;

    fetch(0);
    stage(0);
    __syncthreads();

    const int KT = INTER / 32;   // 16
    for (int kt = 0; kt < KT; kt++) {
        const int p = kt & 1;
        const uint32_t aOff = (uint32_t)p * (128 * 20 * 4);
        if (kt + 1 < KT) fetch((kt + 1) * 16);
#pragma unroll
        for (int kb = 0; kb < 2; kb++) {
            const int p0 = kb * 8;
            uint32_t af[2][4];
            ldsm_x4(af[0], aAddr[0] + aOff + kb * 32);
            ldsm_x4(af[1], aAddr[1] + aOff + kb * 32);
#pragma unroll
            for (int ni = 0; ni < 8; ni++) {
                int nc = wn + ni * 8 + grp;
                uint32_t b0 = Bs32[p][(p0 + tg    ) * 136 + nc];
                uint32_t b1 = Bs32[p][(p0 + tg + 4) * 136 + nc];
#pragma unroll
                for (int mi = 0; mi < 2; mi++) mma_f16(acc[mi][ni], af[mi], b0, b1);
            }
        }
        if (kt + 1 < KT) stage(p ^ 1);
        __syncthreads();
    }

    uint32_t* yout = g_ybuf16 + (size_t)e * CAPACITY * (HID / 2);
#pragma unroll
    for (int mi = 0; mi < 2; mi++) {
#pragma unroll
        for (int half = 0; half < 2; half++) {
            int mrow = m0 + wm + mi * 16 + grp + half * 8;
            if (mrow < Me) {
#pragma unroll
                for (int ni = 0; ni < 8; ni++) {
                    int n = n0 + wn + ni * 8 + tg * 2;
                    yout[(size_t)mrow * (HID / 2) + (n >> 1)] =
                        pack_f16x2(acc[mi][ni][half * 2 + 0], acc[mi][ni][half * 2 + 1]);
                }
            }
        }
    }
}

// ---------------- kernel 5: deterministic combine (fp16 y) ----------------
__global__ void combine_kernel(const float* __restrict__ hs, float* __restrict__ out) {
    const int t = blockIdx.x;
    const int j = threadIdx.x;
    float4 hv = *(const float4*)(hs + (size_t)t * HID + j * 4);
    float zc = g_zeroc[t];
    float4 r;
    r.x = zc * hv.x; r.y = zc * hv.y; r.z = zc * hv.z; r.w = zc * hv.w;
#pragma unroll
    for (int k = 0; k < 2; k++) {
        int p = g_tok_p[t * 2 + k];
        if (p >= 0 && p < CAPACITY) {
            int e = g_tok_e[t * 2 + k];
            float w = g_tok_w[t * 2 + k];
            uint2 yp = *(const uint2*)(g_ybuf16 + ((size_t)e * CAPACITY + p) * (HID / 2) + j * 2);
            float2 y0 = __half22float2(*(const __half2*)&yp.x);
            float2 y1 = __half22float2(*(const __half2*)&yp.y);
            r.x = fmaf(w, y0.x, r.x);
            r.y = fmaf(w, y0.y, r.y);
            r.z = fmaf(w, y1.x, r.z);
            r.w = fmaf(w, y1.y, r.w);
        }
    }
    r.x *= SCALE_F; r.y *= SCALE_F; r.z *= SCALE_F; r.w *= SCALE_F;
    *(float4*)(out + (size_t)t * HID + j * 4) = r;
}

// ---------------- launcher ----------------
extern "C" void kernel_launch(void* const* d_in, const int* in_sizes, int n_in,
                              void* d_out, int out_size) {
    const float* hs   = (const float*)d_in[0];   // [4096,1024]
    const float* rw   = (const float*)d_in[1];   // [80,1024]
    const float* bias = (const float*)d_in[2];   // [80]
    const float* wg   = (const float*)d_in[3];   // [64,1024,512]
    const float* wu   = (const float*)d_in[4];   // [64,1024,512]
    const float* wd   = (const float*)d_in[5];   // [64,512,1024]
    float* out = (float*)d_out;                  // [4096,1024]

    router_gemm_kernel<<<T_TOK / 32, 256>>>(hs, rw);
    topk_dispatch_kernel<<<T_TOK / 8, 256>>>(bias);
    gemm_gateup_kernel<<<dim3(INTER / 64, (CAPACITY + 127) / 128, NE), 256>>>(hs, wg, wu);
    gemm_down_kernel<<<dim3(HID / 128, (CAPACITY + 127) / 128, NE), 256>>>(wd);
    combine_kernel<<<T_TOK, 256>>>(hs, out);
}

// round 13
// speedup vs baseline: 1.2674x; 1.0297x over previous
#include <cuda_runtime.h>
#include <cuda_fp16.h>
#include <cstdint>

#define T_TOK   4096
#define HID     1024
#define INTER   512
#define NE      64
#define NEZ     80
#define CAPACITY 320
#define SCALE_F 1.5f

// ---------------- scratch (static device globals; no allocation) ----------------
__device__ float    g_logits[(size_t)T_TOK * NEZ];
__device__ int      g_counts[NE];
__device__ int      g_rows[NE * CAPACITY];
__device__ int      g_tok_e[T_TOK * 2];
__device__ int      g_tok_p[T_TOK * 2];
__device__ float    g_tok_w[T_TOK * 2];
__device__ float    g_zeroc[T_TOK];
__device__ uint32_t g_gbuf32[(size_t)NE * CAPACITY * (INTER / 2)];  // fp16 k-pairs, 21 MB
__device__ uint32_t g_ybuf16[(size_t)NE * CAPACITY * (HID / 2)];    // fp16 n-pairs, 42 MB

// ---------------- helpers ----------------
__device__ __forceinline__ uint32_t pack_f16x2(float lo, float hi) {
    uint32_t r;
    asm("cvt.rn.f16x2.f32 %0, %1, %2;" : "=r"(r) : "f"(hi), "f"(lo));
    return r;
}
__device__ __forceinline__ void mma_f16(float* c, const uint32_t* a, uint32_t b0, uint32_t b1) {
    asm volatile(
        "mma.sync.aligned.m16n8k16.row.col.f32.f16.f16.f32 "
        "{%0,%1,%2,%3},{%4,%5,%6,%7},{%8,%9},{%0,%1,%2,%3};\n"
        : "+f"(c[0]), "+f"(c[1]), "+f"(c[2]), "+f"(c[3])
        : "r"(a[0]), "r"(a[1]), "r"(a[2]), "r"(a[3]), "r"(b0), "r"(b1));
}
__device__ __forceinline__ void ldsm_x4(uint32_t* r, uint32_t addr) {
    asm volatile("ldmatrix.sync.aligned.m8n8.x4.shared.b16 {%0,%1,%2,%3}, [%4];"
                 : "=r"(r[0]), "=r"(r[1]), "=r"(r[2]), "=r"(r[3]) : "r"(addr));
}
__device__ __forceinline__ void lds_v2(uint32_t& a, uint32_t& b, uint32_t addr) {
    asm volatile("ld.shared.v2.u32 {%0,%1}, [%2];" : "=r"(a), "=r"(b) : "r"(addr));
}
__device__ __forceinline__ float4 ldcg_f4(const float* p) {
    float4 v;
    asm volatile("ld.global.cg.v4.f32 {%0,%1,%2,%3}, [%4];"
                 : "=f"(v.x), "=f"(v.y), "=f"(v.z), "=f"(v.w) : "l"(p));
    return v;
}
__device__ __forceinline__ uint2 ldcg_u2(const uint32_t* p) {
    uint2 v;
    asm volatile("ld.global.cg.v2.u32 {%0,%1}, [%2];" : "=r"(v.x), "=r"(v.y) : "l"(p));
    return v;
}
__device__ __forceinline__ void cp_async16(uint32_t dst, const void* src, int src_bytes) {
    asm volatile("cp.async.cg.shared.global [%0], [%1], 16, %2;"
                 :: "r"(dst), "l"(src), "r"(src_bytes) : "memory");
}
__device__ __forceinline__ void cp_commit() {
    asm volatile("cp.async.commit_group;" ::: "memory");
}
__device__ __forceinline__ void cp_wait0() {
    asm volatile("cp.async.wait_group 0;" ::: "memory");
}

// ---------------- kernel 1: router GEMM (fp32 FFMA, exact selection path) ----------
// BM=32 tokens -> 128 blocks. Block 0 also zeroes the expert counters.
__global__ void __launch_bounds__(256) router_gemm_kernel(
    const float* __restrict__ hs, const float* __restrict__ rw) {
    __shared__ float As[32][33];
    __shared__ float Ws[32][81];
    const int m0 = blockIdx.x * 32;
    const int tid = threadIdx.x;
    const int tm = tid & 15;
    const int tn = tid >> 4;

    if (blockIdx.x == 0 && tid < NE) g_counts[tid] = 0;

    float acc[2][5];
#pragma unroll
    for (int i = 0; i < 2; i++)
#pragma unroll
        for (int j = 0; j < 5; j++) acc[i][j] = 0.f;

    for (int k0 = 0; k0 < HID; k0 += 32) {
#pragma unroll
        for (int i = 0; i < 4; i++) {
            int lin = tid + i * 256;
            int k = lin & 31, m = lin >> 5;
            As[k][m] = hs[(size_t)(m0 + m) * HID + k0 + k];
        }
#pragma unroll
        for (int i = 0; i < 10; i++) {
            int lin = tid + i * 256;
            int k = lin & 31, n = lin >> 5;
            Ws[k][n] = rw[(size_t)n * HID + k0 + k];
        }
        __syncthreads();
#pragma unroll
        for (int kk = 0; kk < 32; kk++) {
            float a[2], w[5];
#pragma unroll
            for (int i = 0; i < 2; i++) a[i] = As[kk][tm + 16 * i];
#pragma unroll
            for (int j = 0; j < 5; j++) w[j] = Ws[kk][tn + 16 * j];
#pragma unroll
            for (int i = 0; i < 2; i++)
#pragma unroll
                for (int j = 0; j < 5; j++) acc[i][j] = fmaf(a[i], w[j], acc[i][j]);
        }
        __syncthreads();
    }
#pragma unroll
    for (int i = 0; i < 2; i++)
#pragma unroll
        for (int j = 0; j < 5; j++)
            g_logits[(size_t)(m0 + tm + 16 * i) * NEZ + tn + 16 * j] = acc[i][j];
}

// ---------------- kernel 2: warp-per-token sigmoid + top-2 + dispatch ----------------
__device__ __forceinline__ bool tk_better(float x, int xi, float y, int yi) {
    return (x > y) || (x == y && xi < yi);
}
__global__ void __launch_bounds__(256) topk_dispatch_kernel(const float* __restrict__ bias) {
    const int warp = threadIdx.x >> 5;
    const int lane = threadIdx.x & 31;
    const int t = blockIdx.x * 8 + warp;
    if (t >= T_TOK) return;

    float b1 = -1e30f, b2 = -1e30f;
    int i1 = NEZ, i2 = NEZ;
#pragma unroll
    for (int c = 0; c < 3; c++) {
        int e = lane + 32 * c;
        if (e < NEZ) {
            float l = g_logits[(size_t)t * NEZ + e];
            float s = 1.f / (1.f + expf(-l));
            float b = s + bias[e];
            if (tk_better(b, e, b1, i1)) { b2 = b1; i2 = i1; b1 = b; i1 = e; }
            else if (tk_better(b, e, b2, i2)) { b2 = b; i2 = e; }
        }
    }
#pragma unroll
    for (int ofs = 16; ofs > 0; ofs >>= 1) {
        float c1 = __shfl_xor_sync(0xFFFFFFFF, b1, ofs);
        int   ci1 = __shfl_xor_sync(0xFFFFFFFF, i1, ofs);
        float c2 = __shfl_xor_sync(0xFFFFFFFF, b2, ofs);
        int   ci2 = __shfl_xor_sync(0xFFFFFFFF, i2, ofs);
        if (tk_better(c1, ci1, b1, i1)) {
            if (tk_better(b1, i1, c2, ci2)) { b2 = b1; i2 = i1; }
            else { b2 = c2; i2 = ci2; }
            b1 = c1; i1 = ci1;
        } else {
            if (tk_better(c1, ci1, b2, i2)) { b2 = c1; i2 = ci1; }
        }
    }

    if (lane == 0) {
        float zc = 0.f;
        int sel[2] = {i1, i2};
#pragma unroll
        for (int k = 0; k < 2; k++) {
            int e = sel[k];
            float l = g_logits[(size_t)t * NEZ + e];
            float w = 1.f / (1.f + expf(-l));
            if (e >= NE) {
                zc += w;
                g_tok_p[t * 2 + k] = -1;
                g_tok_e[t * 2 + k] = 0;
                g_tok_w[t * 2 + k] = 0.f;
            } else {
                int p = atomicAdd(&g_counts[e], 1);
                if (p < CAPACITY) g_rows[e * CAPACITY + p] = t;
                g_tok_p[t * 2 + k] = p;
                g_tok_e[t * 2 + k] = e;
                g_tok_w[t * 2 + k] = w;
            }
        }
        g_zeroc[t] = zc;
    }
}

// ---------------- kernel 3: fused gate/up fp16 GEMM + SiLU -> g_gbuf32 -----------
// Tile 128M x 64N x 32K. ldmatrix A, interleaved g/u B. All global loads .cg.
__global__ void __launch_bounds__(256, 2) gemm_gateup_kernel(
    const float* __restrict__ hs,
    const float* __restrict__ wg,
    const float* __restrict__ wu) {
    const int e = blockIdx.z;
    const int Me = min(g_counts[e], CAPACITY);
    const int m0 = blockIdx.y * 128;
    if (m0 >= Me) return;
    const int n0 = blockIdx.x * 64;

    __shared__ uint32_t As32[2][128 * 20];
    __shared__ uint32_t Bgu[2][16 * 152];
    __shared__ int toks[128];

    const int tid = threadIdx.x;
    const int lane = tid & 31, warp = tid >> 5;
    const int grp = lane >> 2, tg = lane & 3;
    const int wm = (warp >> 1) * 32, wn = (warp & 1) * 32;

    if (tid < 128) {
        int r = m0 + tid;
        toks[tid] = (r < Me) ? g_rows[e * CAPACITY + r] : -1;
    }
    __syncthreads();

    const float* aP[4];
    int aDst[4];
#pragma unroll
    for (int i = 0; i < 4; i++) {
        int slot = tid + i * 256;
        int row = slot >> 3, fq = slot & 7;
        int tok = toks[row];
        aP[i] = (tok >= 0) ? hs + (size_t)tok * HID + fq * 4 : (const float*)0;
        aDst[i] = row * 20 + fq * 2;
    }
    const int j = tid >> 4;
    const int n4 = (tid & 15) * 4;
    const float* gP = wg + (size_t)e * HID * INTER + (size_t)(2 * j) * INTER + n0 + n4;
    const float* uP = wu + (size_t)e * HID * INTER + (size_t)(2 * j) * INTER + n0 + n4;
    const int bDst = j * 152 + n4 * 2;

    const uint32_t asBase = (uint32_t)__cvta_generic_to_shared(&As32[0][0]);
    const uint32_t bBase  = (uint32_t)__cvta_generic_to_shared(&Bgu[0][0]);
    const int rowoff = lane & 15;
    uint32_t aAddr[2];
#pragma unroll
    for (int mi = 0; mi < 2; mi++)
        aAddr[mi] = asBase + (uint32_t)((wm + mi * 16 + rowoff) * 20) * 4 + ((lane >= 16) ? 16 : 0);

    float4 aR[4], gR0, gR1, uR0, uR1;
    auto fetch = [&](int k0) {
#pragma unroll
        for (int i = 0; i < 4; i++)
            aR[i] = aP[i] ? ldcg_f4(aP[i] + k0) : make_float4(0.f, 0.f, 0.f, 0.f);
        gR0 = ldcg_f4(gP + (size_t)k0 * INTER);
        gR1 = ldcg_f4(gP + (size_t)(k0 + 1) * INTER);
        uR0 = ldcg_f4(uP + (size_t)k0 * INTER);
        uR1 = ldcg_f4(uP + (size_t)(k0 + 1) * INTER);
    };
    auto stage = [&](int buf) {
#pragma unroll
        for (int i = 0; i < 4; i++) {
            uint2 v = make_uint2(pack_f16x2(aR[i].x, aR[i].y), pack_f16x2(aR[i].z, aR[i].w));
            *(uint2*)&As32[buf][aDst[i]] = v;
        }
        uint4 v0 = make_uint4(pack_f16x2(gR0.x, gR1.x), pack_f16x2(uR0.x, uR1.x),
                              pack_f16x2(gR0.y, gR1.y), pack_f16x2(uR0.y, uR1.y));
        uint4 v1 = make_uint4(pack_f16x2(gR0.z, gR1.z), pack_f16x2(uR0.z, uR1.z),
                              pack_f16x2(gR0.w, gR1.w), pack_f16x2(uR0.w, uR1.w));
        *(uint4*)&Bgu[buf][bDst] = v0;
        *(uint4*)&Bgu[buf][bDst + 4] = v1;
    };

    float accG[2][4][4], accU[2][4][4];
#pragma unroll
    for (int a = 0; a < 2; a++)
#pragma unroll
        for (int b = 0; b < 4; b++)
#pragma unroll
            for (int c = 0; c < 4; c++) { accG[a][b][c] = 0.f; accU[a][b][c] = 0.f; }

    fetch(0);
    stage(0);
    __syncthreads();

    const int KT = HID / 32;   // 32
    for (int kt = 0; kt < KT; kt++) {
        const int p = kt & 1;
        const uint32_t aOff = (uint32_t)p * (128 * 20 * 4);
        const uint32_t bOff = (uint32_t)p * (16 * 152 * 4);
        if (kt + 1 < KT) fetch((kt + 1) * 32);
#pragma unroll
        for (int kb = 0; kb < 2; kb++) {
            const int p0 = kb * 8;
            uint32_t af[2][4];
            ldsm_x4(af[0], aAddr[0] + aOff + kb * 32);
            ldsm_x4(af[1], aAddr[1] + aOff + kb * 32);
#pragma unroll
            for (int ni = 0; ni < 4; ni++) {
                int nc = wn + ni * 8 + grp;
                uint32_t bg0, bu0, bg1, bu1;
                lds_v2(bg0, bu0, bBase + bOff + (uint32_t)((p0 + tg) * 152 + nc * 2) * 4);
                lds_v2(bg1, bu1, bBase + bOff + (uint32_t)((p0 + tg + 4) * 152 + nc * 2) * 4);
#pragma unroll
                for (int mi = 0; mi < 2; mi++) {
                    mma_f16(accG[mi][ni], af[mi], bg0, bg1);
                    mma_f16(accU[mi][ni], af[mi], bu0, bu1);
                }
            }
        }
        if (kt + 1 < KT) stage(p ^ 1);
        __syncthreads();
    }

    uint32_t* gout = g_gbuf32 + (size_t)e * CAPACITY * (INTER / 2);
#pragma unroll
    for (int mi = 0; mi < 2; mi++) {
#pragma unroll
        for (int half = 0; half < 2; half++) {
            int mrow = m0 + wm + mi * 16 + grp + half * 8;
            if (mrow < Me) {
#pragma unroll
                for (int ni = 0; ni < 4; ni++) {
                    int n = n0 + wn + ni * 8 + tg * 2;
                    float gv0 = accG[mi][ni][half * 2 + 0];
                    float gv1 = accG[mi][ni][half * 2 + 1];
                    float uv0 = accU[mi][ni][half * 2 + 0];
                    float uv1 = accU[mi][ni][half * 2 + 1];
                    float o0 = (gv0 / (1.f + __expf(-gv0))) * uv0;
                    float o1 = (gv1 / (1.f + __expf(-gv1))) * uv1;
                    gout[(size_t)mrow * (INTER / 2) + (n >> 1)] = pack_f16x2(o0, o1);
                }
            }
        }
    }
}

// ---------------- kernel 4: down-proj fp16 GEMM -> y_buf (fp16) ----------------
// Tile 128M x 128N x 32K. A via cp.async.cg (already fp16 in gbuf); B .cg loads.
__global__ void __launch_bounds__(256, 2) gemm_down_kernel(const float* __restrict__ wd) {
    const int e = blockIdx.z;
    const int Me = min(g_counts[e], CAPACITY);
    const int m0 = blockIdx.y * 128;
    if (m0 >= Me) return;
    const int n0 = blockIdx.x * 128;

    __shared__ uint32_t As32[2][128 * 20];   // fp16 kpairs [row][16+4pad]
    __shared__ uint32_t Bs32[2][16 * 136];   // [kpair][128 n + 8 pad]

    const int tid = threadIdx.x;
    const int lane = tid & 31, warp = tid >> 5;
    const int grp = lane >> 2, tg = lane & 3;
    const int wm = (warp & 3) * 32, wn = (warp >> 2) * 64;

    const uint32_t asBase = (uint32_t)__cvta_generic_to_shared(&As32[0][0]);

    // A cp.async: 2 slots/thread, 16B each. slot -> row = slot>>2, q = slot&3.
    const uint32_t* gA = g_gbuf32 + ((size_t)e * CAPACITY + m0) * (INTER / 2);
    const uint32_t* aSrc[2];
    int aOK[2];
    uint32_t aDstAddr[2];
#pragma unroll
    for (int i = 0; i < 2; i++) {
        int slot = tid + i * 256;
        int row = slot >> 2, q = slot & 3;
        aOK[i] = (m0 + row < CAPACITY) ? 16 : 0;
        aSrc[i] = gA + (size_t)row * (INTER / 2) + q * 4;
        aDstAddr[i] = asBase + (uint32_t)(row * 20 + q * 4) * 4;
    }
    // B staging: 2 slots, kpair jj, 4 columns each
    const float* wdBase = wd + (size_t)e * INTER * HID + n0;
    const float* bP[2];
    int bDst[2];
#pragma unroll
    for (int i = 0; i < 2; i++) {
        int slot = tid + i * 256;
        int jj = slot >> 5, ng = slot & 31;
        bP[i] = wdBase + (size_t)(2 * jj) * HID + ng * 4;
        bDst[i] = jj * 136 + ng * 4;
    }

    const int rowoff = lane & 15;
    uint32_t aAddr[2];
#pragma unroll
    for (int mi = 0; mi < 2; mi++)
        aAddr[mi] = asBase + (uint32_t)((wm + mi * 16 + rowoff) * 20) * 4 + ((lane >= 16) ? 16 : 0);

    float4 bR0[2], bR1[2];
    auto issueA = [&](int buf, int kp) {   // kp = kpair (u32) offset
#pragma unroll
        for (int i = 0; i < 2; i++)
            cp_async16(aDstAddr[i] + (uint32_t)buf * (128 * 20 * 4), aSrc[i] + kp, aOK[i]);
        cp_commit();
    };
    auto fetchB = [&](int kt16) {
#pragma unroll
        for (int i = 0; i < 2; i++) {
            bR0[i] = ldcg_f4(bP[i] + (size_t)(kt16 * 2) * HID);
            bR1[i] = ldcg_f4(bP[i] + (size_t)(kt16 * 2 + 1) * HID);
        }
    };
    auto stageB = [&](int buf) {
#pragma unroll
        for (int i = 0; i < 2; i++) {
            uint4 vb = make_uint4(pack_f16x2(bR0[i].x, bR1[i].x), pack_f16x2(bR0[i].y, bR1[i].y),
                                  pack_f16x2(bR0[i].z, bR1[i].z), pack_f16x2(bR0[i].w, bR1[i].w));
            *(uint4*)&Bs32[buf][bDst[i]] = vb;
        }
    };

    float acc[2][8][4];
#pragma unroll
    for (int a = 0; a < 2; a++)
#pragma unroll
        for (int b = 0; b < 8; b++)
#pragma unroll
            for (int c = 0; c < 4; c++) acc[a][b][c] = 0.f;

    issueA(0, 0);
    fetchB(0);
    stageB(0);
    cp_wait0();
    __syncthreads();

    const int KT = INTER / 32;   // 16
    for (int kt = 0; kt < KT; kt++) {
        const int p = kt & 1;
        const uint32_t aOff = (uint32_t)p * (128 * 20 * 4);
        if (kt + 1 < KT) {
            issueA(p ^ 1, (kt + 1) * 16);
            fetchB((kt + 1) * 16);
        }
#pragma unroll
        for (int kb = 0; kb < 2; kb++) {
            const int p0 = kb * 8;
            uint32_t af[2][4];
            ldsm_x4(af[0], aAddr[0] + aOff + kb * 32);
            ldsm_x4(af[1], aAddr[1] + aOff + kb * 32);
#pragma unroll
            for (int ni = 0; ni < 8; ni++) {
                int nc = wn + ni * 8 + grp;
                uint32_t b0 = Bs32[p][(p0 + tg    ) * 136 + nc];
                uint32_t b1 = Bs32[p][(p0 + tg + 4) * 136 + nc];
#pragma unroll
                for (int mi = 0; mi < 2; mi++) mma_f16(acc[mi][ni], af[mi], b0, b1);
            }
        }
        if (kt + 1 < KT) stageB(p ^ 1);
        cp_wait0();
        __syncthreads();
    }

    uint32_t* yout = g_ybuf16 + (size_t)e * CAPACITY * (HID / 2);
#pragma unroll
    for (int mi = 0; mi < 2; mi++) {
#pragma unroll
        for (int half = 0; half < 2; half++) {
            int mrow = m0 + wm + mi * 16 + grp + half * 8;
            if (mrow < Me) {
#pragma unroll
                for (int ni = 0; ni < 8; ni++) {
                    int n = n0 + wn + ni * 8 + tg * 2;
                    yout[(size_t)mrow * (HID / 2) + (n >> 1)] =
                        pack_f16x2(acc[mi][ni][half * 2 + 0], acc[mi][ni][half * 2 + 1]);
                }
            }
        }
    }
}

// ---------------- kernel 5: deterministic combine (fp16 y, .cg reads) ----------------
__global__ void combine_kernel(const float* __restrict__ hs, float* __restrict__ out) {
    const int t = blockIdx.x;
    const int j = threadIdx.x;
    float4 hv = *(const float4*)(hs + (size_t)t * HID + j * 4);
    float zc = g_zeroc[t];
    float4 r;
    r.x = zc * hv.x; r.y = zc * hv.y; r.z = zc * hv.z; r.w = zc * hv.w;
#pragma unroll
    for (int k = 0; k < 2; k++) {
        int p = g_tok_p[t * 2 + k];
        if (p >= 0 && p < CAPACITY) {
            int e = g_tok_e[t * 2 + k];
            float w = g_tok_w[t * 2 + k];
            uint2 yp = ldcg_u2(g_ybuf16 + ((size_t)e * CAPACITY + p) * (HID / 2) + j * 2);
            float2 y0 = __half22float2(*(const __half2*)&yp.x);
            float2 y1 = __half22float2(*(const __half2*)&yp.y);
            r.x = fmaf(w, y0.x, r.x);
            r.y = fmaf(w, y0.y, r.y);
            r.z = fmaf(w, y1.x, r.z);
            r.w = fmaf(w, y1.y, r.w);
        }
    }
    r.x *= SCALE_F; r.y *= SCALE_F; r.z *= SCALE_F; r.w *= SCALE_F;
    *(float4*)(out + (size_t)t * HID + j * 4) = r;
}

// ---------------- launcher ----------------
extern "C" void kernel_launch(void* const* d_in, const int* in_sizes, int n_in,
                              void* d_out, int out_size) {
    const float* hs   = (const float*)d_in[0];   // [4096,1024]
    const float* rw   = (const float*)d_in[1];   // [80,1024]
    const float* bias = (const float*)d_in[2];   // [80]
    const float* wg   = (const float*)d_in[3];   // [64,1024,512]
    const float* wu   = (const float*)d_in[4];   // [64,1024,512]
    const float* wd   = (const float*)d_in[5];   // [64,512,1024]
    float* out = (float*)d_out;                  // [4096,1024]

    router_gemm_kernel<<<T_TOK / 32, 256>>>(hs, rw);
    topk_dispatch_kernel<<<T_TOK / 8, 256>>>(bias);
    gemm_gateup_kernel<<<dim3(INTER / 64, (CAPACITY + 127) / 128, NE), 256>>>(hs, wg, wu);
    gemm_down_kernel<<<dim3(HID / 128, (CAPACITY + 127) / 128, NE), 256>>>(wd);
    combine_kernel<<<T_TOK, 256>>>(hs, out);
}